// round 11
// baseline (speedup 1.0000x reference)
#include <cuda_runtime.h>
#include <cuda_bf16.h>
#include <math.h>

// Fixed problem shapes
constexpr int S  = 20;    // alphabet
constexpr int SS = S * S; // 400
constexpr int MM = 2;     // m
constexpr int KK = 2;     // k
constexpr int NB = 512;   // b
constexpr int LL = 512;   // L
constexpr int NRATES = 512;
constexpr int NT = 20;    // uniformization Taylor terms n = 0..19
constexpr int BPB = 4;    // b's per block

__device__ __forceinline__ float softplusf(float x) {
    return fmaxf(x, 0.0f) + log1pf(expf(-fabsf(x)));
}

// ---------------------------------------------------------------------------
// Single fused kernel. Each block (256 total, 1024 threads, 2/SM):
//   Setup (redundant per block, both k of its m):
//     softmax p, R, Q, row sums d, mue, mu, M = Q/mue + (mu - d/mue)I >= 0,
//     then the 19-step chain C_n = C_{n-1} M / n kept in registers (c[20]).
//   Horner: P(tau_b) = e^{-tau*mu} * sum_n tau^n C_n  -> SMEM (all 4 b's).
//   Store: one uninterrupted stream of 20 independent LDS.128->STG.128 per
//   thread; 320 KB contiguous per block.
// ---------------------------------------------------------------------------
__global__ void __launch_bounds__(1024, 2)
fused_kernel(const int* __restrict__ seq,
             const int* __restrict__ ridx,
             const float* __restrict__ tauk,
             const float* __restrict__ exch,
             const float* __restrict__ equi,
             float4* __restrict__ out4) {
    __shared__ float Msh[KK * SS];          // 800
    __shared__ float bufA[KK * SS];         // Qsh, then C ping
    __shared__ float bufB[KK * SS];         // C pong
    __shared__ float Psh[BPB * KK * SS];    // 3200 floats
    __shared__ int   seqsh[BPB * LL];       // 2048 ints
    __shared__ float psh[KK][S];
    __shared__ float dsh[KK * S];
    __shared__ float s_inv[KK], s_muv[KK];
    __shared__ float s_tau[BPB], s_scale[BPB * KK];

    const int grp = blockIdx.x;             // 0..255
    const int m   = grp >> 7;               // 128 groups per m
    const int b0  = (grp & 127) * BPB;
    const int tid = threadIdx.x;            // 0..1023

    // ---- sequences: 512 int4 loads ----
    if (tid < (BPB * LL) / 4) {
        const int4* sq = (const int4*)(seq + (m * NB + b0) * LL);
        ((int4*)seqsh)[tid] = sq[tid];
    }

    // ---- softmax of equilibrium rows: warp 0 -> k=0, warp 1 -> k=1 ----
    if (tid < 2 * 32) {
        const int kq2 = tid >> 5, lane = tid & 31;
        float q = (lane < S) ? equi[(m * KK + kq2) * S + lane] : -1e30f;
        float mx = q;
#pragma unroll
        for (int o = 16; o; o >>= 1) mx = fmaxf(mx, __shfl_xor_sync(~0u, mx, o));
        float e = (lane < S) ? expf(q - mx) : 0.0f;
        float sm = e;
#pragma unroll
        for (int o = 16; o; o >>= 1) sm += __shfl_xor_sync(~0u, sm, o);
        if (lane < S) psh[kq2][lane] = e / sm;
    }

    // ---- R entries (independent of softmax) ----
    const bool act = tid < KK * SS;
    int kq = 0, i = 0, j = 0;
    float r = 0.0f;
    if (act) {
        kq = tid / SS;
        const int e = tid - kq * SS;
        i = e / S; j = e - i * S;
        const float* E = exch + (m * KK + kq) * SS;
        r = (i == j) ? 0.0f : softplusf(0.5f * (E[i * S + j] + E[j * S + i]));
    }
    __syncthreads();

    // ---- Q off-diagonals ----
    float qv = 0.0f;
    if (act) { qv = r * psh[kq][j]; bufA[tid] = qv; }
    __syncthreads();

    // ---- row sums d (40 rows) ----
    if (tid < KK * S) {
        const int kq2 = tid / S, i2 = tid - kq2 * S;
        float d = 0.0f;
#pragma unroll
        for (int t = 0; t < S; t++) d += bufA[kq2 * SS + i2 * S + t];
        dsh[tid] = d;
    }
    __syncthreads();

    // ---- mue, mu per k (warps 0,1) ----
    if (tid < 2 * 32) {
        const int kq2 = tid >> 5, lane = tid & 31;
        float pd = (lane < S) ? psh[kq2][lane] * dsh[kq2 * S + lane] : 0.0f;
        float mue = pd;
#pragma unroll
        for (int o = 16; o; o >>= 1) mue += __shfl_xor_sync(~0u, mue, o);
        mue = fmaxf(mue, 1e-16f);
        const float inv = 1.0f / mue;
        float dm = (lane < S) ? dsh[kq2 * S + lane] * inv : 0.0f;
#pragma unroll
        for (int o = 16; o; o >>= 1) dm = fmaxf(dm, __shfl_xor_sync(~0u, dm, o));
        if (lane == 0) { s_inv[kq2] = inv; s_muv[kq2] = dm; }
    }
    __syncthreads();

    // ---- M matrix + C_0 = I ; tau + scales (needs s_muv) ----
    float c[NT];
    if (act) {
        const float inv = s_inv[kq], mu = s_muv[kq];
        Msh[tid] = qv * inv + ((i == j) ? (mu - dsh[kq * S + i] * inv) : 0.0f);
        c[0] = (i == j) ? 1.0f : 0.0f;
        bufA[tid] = c[0];                   // overwrite Qsh (no longer needed)
    }
    if (tid < BPB * KK) {
        const int bb = tid >> 1, kk2 = tid & 1;
        const int rb = ridx[m * NB + b0 + bb];
        const float tau = softplusf(tauk[m * NRATES + rb]);
        if (kk2 == 0) s_tau[bb] = tau;
        s_scale[tid] = expf(-tau * s_muv[kk2]);
    }
    __syncthreads();

    // ---- chain: C_n = C_{n-1} @ M / n, kept in registers ----
    float* cur = bufA;
    float* nxt = bufB;
    for (int n = 1; n < NT; n++) {
        if (act) {
            float acc = 0.0f;
#pragma unroll
            for (int t = 0; t < S; t++)
                acc += cur[kq * SS + i * S + t] * Msh[kq * SS + t * S + j];
            acc *= (1.0f / (float)n);
            c[n] = acc;
            nxt[tid] = acc;
        }
        __syncthreads();
        float* tmp = cur; cur = nxt; nxt = tmp;
    }

    // ---- Horner: all BPB P matrices into SMEM ----
    if (act) {
#pragma unroll
        for (int bb = 0; bb < BPB; bb++) {
            const float tau = s_tau[bb];
            float a = c[NT - 1];
#pragma unroll
            for (int n = NT - 2; n >= 0; n--) a = fmaf(a, tau, c[n]);
            Psh[bb * (KK * SS) + tid] = a * s_scale[bb * KK + kq];
        }
    }
    __syncthreads();

    // ---- single uninterrupted store stream ----
    // out[m, b0+bb, l, k, :] = P[bb, k, seq[l], :]
    const float4* P4 = (const float4*)Psh;          // [bb*200 + k2*100 + row*5 + s4]
    float4* ob = out4 + (size_t)(m * NB + b0) * (LL * KK * 5);
#pragma unroll
    for (int bb = 0; bb < BPB; bb++) {
        const int sbase = bb * LL;
        const int pbase = bb * 200;
        const int obase = bb * 5120;
#pragma unroll
        for (int it = 0; it < 5; it++) {
            const int idx = it * 1024 + tid;        // 0..5119 within this b
            const int l   = idx / 10;
            const int rr  = idx - l * 10;
            const int k2  = rr / 5;
            const int s4  = rr - k2 * 5;
            const int row = seqsh[sbase + l];
            ob[obase + idx] = P4[pbase + k2 * 100 + row * 5 + s4];
        }
    }
}

// ---------------------------------------------------------------------------
extern "C" void kernel_launch(void* const* d_in, const int* in_sizes, int n_in,
                              void* d_out, int out_size) {
    const int*   seq  = (const int*)d_in[0];    // (m,b,L) int32
    const int*   ridx = (const int*)d_in[1];    // (m,b) int32
    const float* tauk = (const float*)d_in[2];  // (m,num_rates) f32
    const float* exch = (const float*)d_in[3];  // (m,k,S,S) f32
    const float* equi = (const float*)d_in[4];  // (m,k,S) f32

    fused_kernel<<<MM * (NB / BPB), 1024>>>(seq, ridx, tauk, exch, equi,
                                            (float4*)d_out);
}